// round 3
// baseline (speedup 1.0000x reference)
#include <cuda_runtime.h>
#include <math.h>

// Problem constants
#define BQ   8192
#define DIN  1024
#define NEXP 8
#define DEXP 1024

// ---------------------------------------------------------------------------
// Scratch (static __device__ globals — the sanctioned no-alloc scratch path)
// ---------------------------------------------------------------------------
__device__ int   g_cnt[NEXP];                       // per-expert token counts
__device__ int   g_tok[NEXP * BQ];                  // per-expert token lists
__device__ float g_wt [NEXP * BQ];                  // per-expert gate weights
__device__ float g_h  [(size_t)NEXP * BQ * DEXP];   // hidden activations (256 MB)

// ---------------------------------------------------------------------------
// f32x2 packed-FMA helpers (FFMA2 — 2x fp32 rate, only reachable via PTX)
// ---------------------------------------------------------------------------
__device__ __forceinline__ unsigned long long pkdup(float v) {
    unsigned long long r;
    unsigned u = __float_as_uint(v);
    asm("mov.b64 %0, {%1, %1};" : "=l"(r) : "r"(u));
    return r;
}
__device__ __forceinline__ unsigned long long pk2(float a, float b) {
    unsigned long long r;
    asm("mov.b64 %0, {%1, %2};" : "=l"(r)
        : "r"(__float_as_uint(a)), "r"(__float_as_uint(b)));
    return r;
}
__device__ __forceinline__ void fma2(unsigned long long& d,
                                     unsigned long long a,
                                     unsigned long long b) {
    asm("fma.rn.f32x2 %0, %1, %2, %0;" : "+l"(d) : "l"(a), "l"(b));
}
__device__ __forceinline__ float2 unpk(unsigned long long v) {
    unsigned lo, hi;
    asm("mov.b64 {%0, %1}, %2;" : "=r"(lo), "=r"(hi) : "l"(v));
    return make_float2(__uint_as_float(lo), __uint_as_float(hi));
}

// ---------------------------------------------------------------------------
// Kernel 1: zero the MoE output region and the routing counters
// ---------------------------------------------------------------------------
__global__ void init_kernel(float* __restrict__ out) {
    int i = blockIdx.x * blockDim.x + threadIdx.x;
    if (i < BQ * DEXP) out[i] = 0.0f;
    if (i < NEXP)      g_cnt[i] = 0;
}

// ---------------------------------------------------------------------------
// Kernel 2: gating — logits, top-2, softmax, routing, gate_weights scatter
// One block per token, 256 threads.
// ---------------------------------------------------------------------------
__global__ __launch_bounds__(256)
void gate_kernel(const float* __restrict__ x, const float* __restrict__ gw,
                 float* __restrict__ gate_out) {
    const int b   = blockIdx.x;
    const int tid = threadIdx.x;
    const float* xr = x + (size_t)b * DIN;

    float acc[8];
#pragma unroll
    for (int e = 0; e < 8; e++) acc[e] = 0.0f;

    for (int k = tid; k < DIN; k += 256) {
        float xv = xr[k];
        float4 g0 = *(const float4*)(gw + k * 8);
        float4 g1 = *(const float4*)(gw + k * 8 + 4);
        acc[0] += xv * g0.x; acc[1] += xv * g0.y;
        acc[2] += xv * g0.z; acc[3] += xv * g0.w;
        acc[4] += xv * g1.x; acc[5] += xv * g1.y;
        acc[6] += xv * g1.z; acc[7] += xv * g1.w;
    }

    // warp reduction
#pragma unroll
    for (int e = 0; e < 8; e++)
#pragma unroll
        for (int off = 16; off > 0; off >>= 1)
            acc[e] += __shfl_down_sync(0xffffffffu, acc[e], off);

    __shared__ float wpart[8][8];
    __shared__ float logits[8];
    __shared__ float sw[2];
    __shared__ int   si[2];
    const int warp = tid >> 5, lane = tid & 31;
    if (lane == 0) {
#pragma unroll
        for (int e = 0; e < 8; e++) wpart[warp][e] = acc[e];
    }
    __syncthreads();
    if (tid < 8) {
        float s = 0.0f;
#pragma unroll
        for (int w = 0; w < 8; w++) s += wpart[w][tid];
        logits[tid] = s;
    }
    __syncthreads();

    if (tid == 0) {
        // top-2, ties -> lowest index (matches jax.lax.top_k)
        int i0 = 0; float v0 = logits[0];
#pragma unroll
        for (int e = 1; e < 8; e++) if (logits[e] > v0) { v0 = logits[e]; i0 = e; }
        int i1 = -1; float v1 = -3.4e38f;
#pragma unroll
        for (int e = 0; e < 8; e++)
            if (e != i0 && logits[e] > v1) { v1 = logits[e]; i1 = e; }

        // softmax over the two top logits
        float ex  = expf(v1 - v0);
        float inv = 1.0f / (1.0f + ex);
        float w0 = inv, w1 = ex * inv;
        si[0] = i0; si[1] = i1; sw[0] = w0; sw[1] = w1;

        int p0 = atomicAdd(&g_cnt[i0], 1);
        g_tok[i0 * BQ + p0] = b; g_wt[i0 * BQ + p0] = w0;
        int p1 = atomicAdd(&g_cnt[i1], 1);
        g_tok[i1 * BQ + p1] = b; g_wt[i1 * BQ + p1] = w1;
    }
    __syncthreads();

    if (tid < 8) {
        float v = (tid == si[0]) ? sw[0] : ((tid == si[1]) ? sw[1] : 0.0f);
        gate_out[(size_t)b * 8 + tid] = v;
    }
}

// ---------------------------------------------------------------------------
// GEMM tiling shared by both expert GEMMs:
//   BM=128, BN=128, BK=16, 256 threads (16x16), 8x8 per-thread microtile,
//   split-tile layout (halves at +0 and +64) for conflict-light LDS.128.
// Grid: x = expert * 64 + m_tile (B/128 = 64 tiles, early-exit on count),
//       y = n_tile (DEXP/128 = 8).
// ---------------------------------------------------------------------------

// Kernel 3: h = gelu(x[gathered] @ w1[e] + b1[e])
__global__ __launch_bounds__(256, 2)
void gemm1_kernel(const float* __restrict__ x, const float* __restrict__ w1,
                  const float* __restrict__ b1) {
    const int e    = blockIdx.x >> 6;
    const int tm   = blockIdx.x & 63;
    const int cnt  = g_cnt[e];
    const int row0 = tm * 128;
    if (row0 >= cnt) return;
    const int n0 = blockIdx.y * 128;

    __shared__ float As[16][128];
    __shared__ float Bs[16][128];
    __shared__ int   tok_s[128];

    const int tid = threadIdx.x;
    const int tx  = tid & 15;
    const int ty  = tid >> 4;

    if (tid < 128) {
        int r = row0 + tid;
        tok_s[tid] = (r < cnt) ? g_tok[e * BQ + r] : g_tok[e * BQ + row0];
    }
    __syncthreads();

    const int lm  = tid >> 1;          // row this thread loads for As
    const int lk  = (tid & 1) * 8;     // k offset within BK
    const int bkr = tid >> 5;          // k row for Bs (and +8)
    const int bn4 = (tid & 31) * 4;    // n offset for Bs

    const float* arow  = x + (size_t)tok_s[lm] * DIN + lk;
    const float* brow  = w1 + (size_t)e * DIN * DEXP + (size_t)bkr * DEXP + n0 + bn4;

    unsigned long long acc[8][4];
#pragma unroll
    for (int i = 0; i < 8; i++)
#pragma unroll
        for (int j = 0; j < 4; j++) acc[i][j] = 0ull;

    for (int k0 = 0; k0 < DIN; k0 += 16) {
        float4 a0  = *(const float4*)(arow + k0);
        float4 a1  = *(const float4*)(arow + k0 + 4);
        float4 bb0 = *(const float4*)(brow + (size_t)k0 * DEXP);
        float4 bb1 = *(const float4*)(brow + (size_t)(k0 + 8) * DEXP);
        __syncthreads();
        As[lk + 0][lm] = a0.x; As[lk + 1][lm] = a0.y;
        As[lk + 2][lm] = a0.z; As[lk + 3][lm] = a0.w;
        As[lk + 4][lm] = a1.x; As[lk + 5][lm] = a1.y;
        As[lk + 6][lm] = a1.z; As[lk + 7][lm] = a1.w;
        *(float4*)&Bs[bkr][bn4]     = bb0;
        *(float4*)&Bs[bkr + 8][bn4] = bb1;
        __syncthreads();
#pragma unroll
        for (int kk = 0; kk < 16; kk++) {
            float4 af0 = *(const float4*)&As[kk][ty * 4];
            float4 af1 = *(const float4*)&As[kk][64 + ty * 4];
            float4 bf0 = *(const float4*)&Bs[kk][tx * 4];
            float4 bf1 = *(const float4*)&Bs[kk][64 + tx * 4];
            unsigned long long bv[4];
            bv[0] = pk2(bf0.x, bf0.y); bv[1] = pk2(bf0.z, bf0.w);
            bv[2] = pk2(bf1.x, bf1.y); bv[3] = pk2(bf1.z, bf1.w);
            float am[8] = {af0.x, af0.y, af0.z, af0.w,
                           af1.x, af1.y, af1.z, af1.w};
#pragma unroll
            for (int i = 0; i < 8; i++) {
                unsigned long long av = pkdup(am[i]);
                fma2(acc[i][0], av, bv[0]);
                fma2(acc[i][1], av, bv[1]);
                fma2(acc[i][2], av, bv[2]);
                fma2(acc[i][3], av, bv[3]);
            }
        }
    }

    float bias[8];
#pragma unroll
    for (int j = 0; j < 4; j++) {
        bias[j]     = b1[e * DEXP + n0 + tx * 4 + j];
        bias[4 + j] = b1[e * DEXP + n0 + 64 + tx * 4 + j];
    }
#pragma unroll
    for (int i = 0; i < 8; i++) {
        int m   = (i < 4) ? (ty * 4 + i) : (64 + ty * 4 + (i - 4));
        int row = row0 + m;
        if (row >= cnt) continue;
        float v[8]; float2 t;
        t = unpk(acc[i][0]); v[0] = t.x; v[1] = t.y;
        t = unpk(acc[i][1]); v[2] = t.x; v[3] = t.y;
        t = unpk(acc[i][2]); v[4] = t.x; v[5] = t.y;
        t = unpk(acc[i][3]); v[6] = t.x; v[7] = t.y;
#pragma unroll
        for (int j = 0; j < 8; j++) {
            float z = v[j] + bias[j];
            v[j] = 0.5f * z * (1.0f + erff(z * 0.70710678118654752f)); // exact gelu
        }
        float* hr = g_h + ((size_t)e * BQ + row) * DEXP + n0;
        *(float4*)(hr + tx * 4)      = make_float4(v[0], v[1], v[2], v[3]);
        *(float4*)(hr + 64 + tx * 4) = make_float4(v[4], v[5], v[6], v[7]);
    }
}

// Kernel 4: out[token] += gate_w * (h @ w2[e] + b2[e])
__global__ __launch_bounds__(256, 2)
void gemm2_kernel(const float* __restrict__ w2, const float* __restrict__ b2,
                  float* __restrict__ out) {
    const int e    = blockIdx.x >> 6;
    const int tm   = blockIdx.x & 63;
    const int cnt  = g_cnt[e];
    const int row0 = tm * 128;
    if (row0 >= cnt) return;
    const int n0 = blockIdx.y * 128;

    __shared__ float As[16][128];
    __shared__ float Bs[16][128];
    __shared__ int   tok_s[128];
    __shared__ float wt_s[128];

    const int tid = threadIdx.x;
    const int tx  = tid & 15;
    const int ty  = tid >> 4;

    if (tid < 128) {
        int r = row0 + tid;
        if (r < cnt) { tok_s[tid] = g_tok[e * BQ + r]; wt_s[tid] = g_wt[e * BQ + r]; }
        else         { tok_s[tid] = 0;                 wt_s[tid] = 0.0f; }
    }
    __syncthreads();

    const int lm  = tid >> 1;
    const int lk  = (tid & 1) * 8;
    const int bkr = tid >> 5;
    const int bn4 = (tid & 31) * 4;

    const float* arow = g_h + ((size_t)e * BQ + row0 + lm) * DEXP + lk;
    const float* brow = w2 + (size_t)e * DEXP * DEXP + (size_t)bkr * DEXP + n0 + bn4;

    unsigned long long acc[8][4];
#pragma unroll
    for (int i = 0; i < 8; i++)
#pragma unroll
        for (int j = 0; j < 4; j++) acc[i][j] = 0ull;

    for (int k0 = 0; k0 < DEXP; k0 += 16) {
        float4 a0  = *(const float4*)(arow + k0);
        float4 a1  = *(const float4*)(arow + k0 + 4);
        float4 bb0 = *(const float4*)(brow + (size_t)k0 * DEXP);
        float4 bb1 = *(const float4*)(brow + (size_t)(k0 + 8) * DEXP);
        __syncthreads();
        As[lk + 0][lm] = a0.x; As[lk + 1][lm] = a0.y;
        As[lk + 2][lm] = a0.z; As[lk + 3][lm] = a0.w;
        As[lk + 4][lm] = a1.x; As[lk + 5][lm] = a1.y;
        As[lk + 6][lm] = a1.z; As[lk + 7][lm] = a1.w;
        *(float4*)&Bs[bkr][bn4]     = bb0;
        *(float4*)&Bs[bkr + 8][bn4] = bb1;
        __syncthreads();
#pragma unroll
        for (int kk = 0; kk < 16; kk++) {
            float4 af0 = *(const float4*)&As[kk][ty * 4];
            float4 af1 = *(const float4*)&As[kk][64 + ty * 4];
            float4 bf0 = *(const float4*)&Bs[kk][tx * 4];
            float4 bf1 = *(const float4*)&Bs[kk][64 + tx * 4];
            unsigned long long bv[4];
            bv[0] = pk2(bf0.x, bf0.y); bv[1] = pk2(bf0.z, bf0.w);
            bv[2] = pk2(bf1.x, bf1.y); bv[3] = pk2(bf1.z, bf1.w);
            float am[8] = {af0.x, af0.y, af0.z, af0.w,
                           af1.x, af1.y, af1.z, af1.w};
#pragma unroll
            for (int i = 0; i < 8; i++) {
                unsigned long long av = pkdup(am[i]);
                fma2(acc[i][0], av, bv[0]);
                fma2(acc[i][1], av, bv[1]);
                fma2(acc[i][2], av, bv[2]);
                fma2(acc[i][3], av, bv[3]);
            }
        }
    }

    float bias[8];
#pragma unroll
    for (int j = 0; j < 4; j++) {
        bias[j]     = b2[e * DEXP + n0 + tx * 4 + j];
        bias[4 + j] = b2[e * DEXP + n0 + 64 + tx * 4 + j];
    }
#pragma unroll
    for (int i = 0; i < 8; i++) {
        int m   = (i < 4) ? (ty * 4 + i) : (64 + ty * 4 + (i - 4));
        int row = row0 + m;
        if (row >= cnt) continue;
        float wgt = wt_s[m];
        int   tk  = tok_s[m];
        float v[8]; float2 t;
        t = unpk(acc[i][0]); v[0] = t.x; v[1] = t.y;
        t = unpk(acc[i][1]); v[2] = t.x; v[3] = t.y;
        t = unpk(acc[i][2]); v[4] = t.x; v[5] = t.y;
        t = unpk(acc[i][3]); v[6] = t.x; v[7] = t.y;
        float* orow = out + (size_t)tk * DEXP + n0;
#pragma unroll
        for (int j = 0; j < 8; j++) {
            int n = (j < 4) ? (tx * 4 + j) : (64 + tx * 4 + (j - 4));
            atomicAdd(&orow[n], (v[j] + bias[j]) * wgt);
        }
    }
}

// ---------------------------------------------------------------------------
// Launch: output layout = [moe_output (B*DEXP) | gate_weights (B*NEXP)]
// ---------------------------------------------------------------------------
extern "C" void kernel_launch(void* const* d_in, const int* in_sizes, int n_in,
                              void* d_out, int out_size) {
    const float* x  = (const float*)d_in[0];
    const float* gw = (const float*)d_in[1];
    const float* w1 = (const float*)d_in[2];
    const float* b1 = (const float*)d_in[3];
    const float* w2 = (const float*)d_in[4];
    const float* b2 = (const float*)d_in[5];
    float* out      = (float*)d_out;
    float* gate_out = out + (size_t)BQ * DEXP;

    init_kernel<<<(BQ * DEXP + 255) / 256, 256>>>(out);
    gate_kernel<<<BQ, 256>>>(x, gw, gate_out);

    dim3 grid(NEXP * (BQ / 128), DEXP / 128);
    gemm1_kernel<<<grid, 256>>>(x, w1, b1);
    gemm2_kernel<<<grid, 256>>>(w2, b2, out);
}

// round 5
// speedup vs baseline: 1.7182x; 1.7182x over previous
#include <cuda_runtime.h>
#include <cuda_bf16.h>
#include <math.h>
#include <stdint.h>

#define BQ   8192
#define DIN  1024
#define NEXP 8
#define DEXP 1024

// GEMM tiling
#define BK        32
#define NCHUNK    32          // 1024 / BK
#define ROWB      80          // SMEM row stride bytes (32 bf16 + 8 pad)
#define ARR_B     (128 * ROWB)        // 10240 B per array
#define STAGE_B   (4 * ARR_B)         // Ah|Al|Bh|Bl = 40960 B
#define NSTAGE    3
#define TOK_OFF   (NSTAGE * STAGE_B)  // 122880
#define SMEM_T    (TOK_OFF + 1024)

// ---------------------------------------------------------------------------
// Static device scratch (sanctioned no-alloc path)
// ---------------------------------------------------------------------------
__device__ int   g_cnt[NEXP];
__device__ int   g_tok[NEXP * BQ];
__device__ float g_wt [NEXP * BQ];
__device__ int   g_asn[BQ * 2];
__device__ __align__(256) __nv_bfloat16 g_xhi [(size_t)BQ * DIN];
__device__ __align__(256) __nv_bfloat16 g_xlo [(size_t)BQ * DIN];
__device__ __align__(256) __nv_bfloat16 g_w1hi[(size_t)NEXP * DIN * DEXP];
__device__ __align__(256) __nv_bfloat16 g_w1lo[(size_t)NEXP * DIN * DEXP];
__device__ __align__(256) __nv_bfloat16 g_w2hi[(size_t)NEXP * DEXP * DEXP];
__device__ __align__(256) __nv_bfloat16 g_w2lo[(size_t)NEXP * DEXP * DEXP];
__device__ __align__(256) __nv_bfloat16 g_hhi [(size_t)NEXP * BQ * DEXP];
__device__ __align__(256) __nv_bfloat16 g_hlo [(size_t)NEXP * BQ * DEXP];
__device__ __align__(256) float         g_y   [(size_t)NEXP * BQ * DEXP];

// ---------------------------------------------------------------------------
// PTX helpers (sm_103-base-target safe: mma.sync / ldmatrix / cp.async only)
// ---------------------------------------------------------------------------
__device__ __forceinline__ uint32_t smem_u32(const void* p) {
    uint32_t a;
    asm("{ .reg .u64 t; cvta.to.shared.u64 t, %1; cvt.u32.u64 %0, t; }"
        : "=r"(a) : "l"(p));
    return a;
}
#define CPASYNC(dst, src) \
    asm volatile("cp.async.cg.shared.global [%0], [%1], 16;" \
                 :: "r"(dst), "l"(src) : "memory")
#define CPCOMMIT()  asm volatile("cp.async.commit_group;" ::: "memory")
#define CPWAIT1()   asm volatile("cp.async.wait_group 1;" ::: "memory")
#define CPWAIT0()   asm volatile("cp.async.wait_group 0;" ::: "memory")

__device__ __forceinline__ void ldm4(uint32_t* r, uint32_t addr) {
    asm volatile("ldmatrix.sync.aligned.m8n8.x4.shared.b16 {%0,%1,%2,%3}, [%4];"
                 : "=r"(r[0]), "=r"(r[1]), "=r"(r[2]), "=r"(r[3]) : "r"(addr));
}
__device__ __forceinline__ void mma_bf16(float* d, const uint32_t* a, const uint32_t* b) {
    asm volatile(
        "mma.sync.aligned.m16n8k16.row.col.f32.bf16.bf16.f32 "
        "{%0,%1,%2,%3}, {%4,%5,%6,%7}, {%8,%9}, {%0,%1,%2,%3};"
        : "+f"(d[0]), "+f"(d[1]), "+f"(d[2]), "+f"(d[3])
        : "r"(a[0]), "r"(a[1]), "r"(a[2]), "r"(a[3]), "r"(b[0]), "r"(b[1]));
}
__device__ __forceinline__ uint32_t pkbf2(float a, float b) {
    return (uint32_t)__bfloat16_as_ushort(__float2bfloat16(a))
         | ((uint32_t)__bfloat16_as_ushort(__float2bfloat16(b)) << 16);
}

// ---------------------------------------------------------------------------
// Kernel: zero routing counters
// ---------------------------------------------------------------------------
__global__ void init_kernel() {
    if (threadIdx.x < NEXP) g_cnt[threadIdx.x] = 0;
}

// ---------------------------------------------------------------------------
// Kernel: gating (logits, top-2, softmax, routing, assignment ids)
// ---------------------------------------------------------------------------
__global__ __launch_bounds__(256)
void gate_kernel(const float* __restrict__ x, const float* __restrict__ gw,
                 float* __restrict__ gate_out) {
    const int b   = blockIdx.x;
    const int tid = threadIdx.x;
    const float* xr = x + (size_t)b * DIN;

    float acc[8];
#pragma unroll
    for (int e = 0; e < 8; e++) acc[e] = 0.0f;
    for (int k = tid; k < DIN; k += 256) {
        float xv = xr[k];
        float4 g0 = *(const float4*)(gw + k * 8);
        float4 g1 = *(const float4*)(gw + k * 8 + 4);
        acc[0] += xv * g0.x; acc[1] += xv * g0.y;
        acc[2] += xv * g0.z; acc[3] += xv * g0.w;
        acc[4] += xv * g1.x; acc[5] += xv * g1.y;
        acc[6] += xv * g1.z; acc[7] += xv * g1.w;
    }
#pragma unroll
    for (int e = 0; e < 8; e++)
#pragma unroll
        for (int off = 16; off > 0; off >>= 1)
            acc[e] += __shfl_down_sync(0xffffffffu, acc[e], off);

    __shared__ float wpart[8][8];
    __shared__ float logits[8];
    __shared__ float sw[2];
    __shared__ int   si[2];
    const int warp = tid >> 5, lane = tid & 31;
    if (lane == 0)
#pragma unroll
        for (int e = 0; e < 8; e++) wpart[warp][e] = acc[e];
    __syncthreads();
    if (tid < 8) {
        float s = 0.0f;
#pragma unroll
        for (int w = 0; w < 8; w++) s += wpart[w][tid];
        logits[tid] = s;
    }
    __syncthreads();

    if (tid == 0) {
        int i0 = 0; float v0 = logits[0];
#pragma unroll
        for (int e = 1; e < 8; e++) if (logits[e] > v0) { v0 = logits[e]; i0 = e; }
        int i1 = -1; float v1 = -3.4e38f;
#pragma unroll
        for (int e = 0; e < 8; e++)
            if (e != i0 && logits[e] > v1) { v1 = logits[e]; i1 = e; }
        float ex  = expf(v1 - v0);
        float inv = 1.0f / (1.0f + ex);
        float w0 = inv, w1 = ex * inv;
        si[0] = i0; si[1] = i1; sw[0] = w0; sw[1] = w1;
        int p0 = atomicAdd(&g_cnt[i0], 1);
        g_tok[i0 * BQ + p0] = b; g_wt[i0 * BQ + p0] = w0; g_asn[2 * b]     = i0 * BQ + p0;
        int p1 = atomicAdd(&g_cnt[i1], 1);
        g_tok[i1 * BQ + p1] = b; g_wt[i1 * BQ + p1] = w1; g_asn[2 * b + 1] = i1 * BQ + p1;
    }
    __syncthreads();
    if (tid < 8) {
        float v = (tid == si[0]) ? sw[0] : ((tid == si[1]) ? sw[1] : 0.0f);
        gate_out[(size_t)b * 8 + tid] = v;
    }
}

// ---------------------------------------------------------------------------
// Kernel: split x into bf16 hi/lo
// ---------------------------------------------------------------------------
__global__ __launch_bounds__(256)
void convert_x_kernel(const float* __restrict__ x) {
    size_t i = ((size_t)blockIdx.x * 256 + threadIdx.x) * 4;
    float4 v = *(const float4*)(x + i);
    __nv_bfloat16 h0 = __float2bfloat16(v.x), h1 = __float2bfloat16(v.y);
    __nv_bfloat16 h2 = __float2bfloat16(v.z), h3 = __float2bfloat16(v.w);
    uint2 hp, lp;
    hp.x = (uint32_t)__bfloat16_as_ushort(h0) | ((uint32_t)__bfloat16_as_ushort(h1) << 16);
    hp.y = (uint32_t)__bfloat16_as_ushort(h2) | ((uint32_t)__bfloat16_as_ushort(h3) << 16);
    lp.x = pkbf2(v.x - __bfloat162float(h0), v.y - __bfloat162float(h1));
    lp.y = pkbf2(v.z - __bfloat162float(h2), v.w - __bfloat162float(h3));
    *(uint2*)(g_xhi + i) = hp;
    *(uint2*)(g_xlo + i) = lp;
}

// ---------------------------------------------------------------------------
// Kernel: transpose + split w1/w2 -> [e][n][k] bf16 hi/lo
// ---------------------------------------------------------------------------
__global__ void convert_w_kernel(const float* __restrict__ w1,
                                 const float* __restrict__ w2) {
    __shared__ float t[32][33];
    const int z = blockIdx.z;
    const float* src = (z < 8 ? w1 : w2) + (size_t)(z & 7) * DIN * DEXP;
    __nv_bfloat16* dh = (z < 8 ? g_w1hi : g_w2hi) + (size_t)(z & 7) * DIN * DEXP;
    __nv_bfloat16* dl = (z < 8 ? g_w1lo : g_w2lo) + (size_t)(z & 7) * DIN * DEXP;
    const int n0 = blockIdx.x * 32, k0 = blockIdx.y * 32;
    const int tx = threadIdx.x, ty = threadIdx.y;
#pragma unroll
    for (int j = 0; j < 32; j += 8)
        t[ty + j][tx] = src[(size_t)(k0 + ty + j) * DEXP + n0 + tx];
    __syncthreads();
#pragma unroll
    for (int j = 0; j < 32; j += 8) {
        float v = t[tx][ty + j];
        __nv_bfloat16 hb = __float2bfloat16(v);
        size_t o = (size_t)(n0 + ty + j) * DIN + k0 + tx;
        dh[o] = hb;
        dl[o] = __float2bfloat16(v - __bfloat162float(hb));
    }
}

// ---------------------------------------------------------------------------
// mma.sync GEMM kernels: 128x128 tile, BK=32, 3-stage cp.async pipeline.
// 8 warps: warp m = wid>>2 (64 rows), warp n = wid&3 (32 cols).
// 3-term bf16 split per k16: D += Ah*Bh + Al*Bh + Ah*Bl.
// grid: x = e*64 + m_tile (early exit), y = n_tile (8).
// ---------------------------------------------------------------------------
struct FragPtrs {
    const __nv_bfloat16 *ah0, *ah1, *al0, *al1, *bh0, *bh1, *bl0, *bl1;
};

__device__ __forceinline__ void load_stage(uint32_t st, const FragPtrs& p,
                                           int k0, uint32_t so0, uint32_t so1) {
    CPASYNC(st + so0,              p.ah0 + k0);
    CPASYNC(st + so1,              p.ah1 + k0);
    CPASYNC(st + ARR_B + so0,      p.al0 + k0);
    CPASYNC(st + ARR_B + so1,      p.al1 + k0);
    CPASYNC(st + 2 * ARR_B + so0,  p.bh0 + k0);
    CPASYNC(st + 2 * ARR_B + so1,  p.bh1 + k0);
    CPASYNC(st + 3 * ARR_B + so0,  p.bl0 + k0);
    CPASYNC(st + 3 * ARR_B + so1,  p.bl1 + k0);
    CPCOMMIT();
}

__device__ __forceinline__ void compute_chunk(uint32_t st, uint32_t aoff,
                                              uint32_t boff, float acc[4][4][4]) {
#pragma unroll
    for (int kk = 0; kk < 2; ++kk) {
        uint32_t ah[4][4], al[4][4], bh[2][4], bl[2][4];
#pragma unroll
        for (int i = 0; i < 4; ++i) {
            ldm4(ah[i], st + aoff + i * (16 * ROWB) + kk * 32);
            ldm4(al[i], st + ARR_B + aoff + i * (16 * ROWB) + kk * 32);
        }
#pragma unroll
        for (int pp = 0; pp < 2; ++pp) {
            ldm4(bh[pp], st + 2 * ARR_B + boff + pp * (16 * ROWB) + kk * 32);
            ldm4(bl[pp], st + 3 * ARR_B + boff + pp * (16 * ROWB) + kk * 32);
        }
#pragma unroll
        for (int i = 0; i < 4; ++i)
#pragma unroll
            for (int nt = 0; nt < 4; ++nt) {
                const uint32_t* bhf = &bh[nt >> 1][(nt & 1) * 2];
                const uint32_t* blf = &bl[nt >> 1][(nt & 1) * 2];
                mma_bf16(acc[i][nt], ah[i], bhf);
                mma_bf16(acc[i][nt], al[i], bhf);
                mma_bf16(acc[i][nt], ah[i], blf);
            }
    }
}

__global__ __launch_bounds__(256)
void gemm1_mma(const float* __restrict__ b1) {
    extern __shared__ char sm[];
    const int e    = blockIdx.x >> 6;
    const int tm   = blockIdx.x & 63;
    const int cnt  = g_cnt[e];
    const int row0 = tm * 128;
    if (row0 >= cnt) return;
    const int n0  = blockIdx.y * 128;
    const int tid = threadIdx.x;
    const int wid = tid >> 5, lane = tid & 31;
    const int wm = wid >> 2, wn = wid & 3;

    const uint32_t sbase = smem_u32(sm);
    int* tok_s = (int*)(sm + TOK_OFF);
    if (tid < 128) {
        int r = row0 + tid;
        tok_s[tid] = (r < cnt) ? g_tok[e * BQ + r] : g_tok[e * BQ + row0];
    }
    __syncthreads();

    // cp.async mapping: thread covers rows crow, crow+64, 16B seg cseg
    const int crow = tid >> 2, cseg = tid & 3;
    const uint32_t so0 = crow * ROWB + cseg * 16;
    const uint32_t so1 = (crow + 64) * ROWB + cseg * 16;
    FragPtrs p;
    {
        size_t a0 = (size_t)tok_s[crow] * DIN + cseg * 8;
        size_t a1 = (size_t)tok_s[crow + 64] * DIN + cseg * 8;
        size_t b0 = ((size_t)e * DEXP + n0 + crow) * DIN + cseg * 8;
        size_t b1o = ((size_t)e * DEXP + n0 + crow + 64) * DIN + cseg * 8;
        p.ah0 = g_xhi + a0;  p.ah1 = g_xhi + a1;
        p.al0 = g_xlo + a0;  p.al1 = g_xlo + a1;
        p.bh0 = g_w1hi + b0; p.bh1 = g_w1hi + b1o;
        p.bl0 = g_w1lo + b0; p.bl1 = g_w1lo + b1o;
    }

    // ldmatrix per-thread offsets
    const uint32_t aoff = (wm * 64 + (lane & 15)) * ROWB + (lane >> 4) * 16;
    const uint32_t boff = (wn * 32 + ((lane >> 4) << 3) + (lane & 7)) * ROWB
                        + ((lane >> 3) & 1) * 16;

    float acc[4][4][4];
#pragma unroll
    for (int i = 0; i < 4; ++i)
#pragma unroll
        for (int j = 0; j < 4; ++j)
#pragma unroll
            for (int q = 0; q < 4; ++q) acc[i][j][q] = 0.0f;

    load_stage(sbase, p, 0, so0, so1);
    load_stage(sbase + STAGE_B, p, BK, so0, so1);
#pragma unroll 1
    for (int c = 0; c < NCHUNK; ++c) {
        if (c + 2 < NCHUNK) CPWAIT1(); else CPWAIT0();
        __syncthreads();
        if (c + 2 < NCHUNK)
            load_stage(sbase + ((c + 2) % 3) * STAGE_B, p, (c + 2) * BK, so0, so1);
        compute_chunk(sbase + (c % 3) * STAGE_B, aoff, boff, acc);
        __syncthreads();
    }

    // epilogue: bias + exact gelu, split to bf16 hi/lo, write h
    float bias[4][2];
#pragma unroll
    for (int nt = 0; nt < 4; ++nt) {
        int c0 = n0 + wn * 32 + nt * 8 + (lane & 3) * 2;
        bias[nt][0] = b1[e * DEXP + c0];
        bias[nt][1] = b1[e * DEXP + c0 + 1];
    }
#pragma unroll
    for (int i = 0; i < 4; ++i) {
#pragma unroll
        for (int half = 0; half < 2; ++half) {
            int r = wm * 64 + i * 16 + (lane >> 2) + half * 8;
            if (row0 + r >= cnt) continue;
            size_t rowbase = ((size_t)e * BQ + row0 + r) * DEXP;
#pragma unroll
            for (int nt = 0; nt < 4; ++nt) {
                int c0 = n0 + wn * 32 + nt * 8 + (lane & 3) * 2;
                float z0 = acc[i][nt][half * 2]     + bias[nt][0];
                float z1 = acc[i][nt][half * 2 + 1] + bias[nt][1];
                float gl0 = 0.5f * z0 * (1.0f + erff(z0 * 0.70710678118654752f));
                float gl1 = 0.5f * z1 * (1.0f + erff(z1 * 0.70710678118654752f));
                __nv_bfloat16 hb0 = __float2bfloat16(gl0);
                __nv_bfloat16 hb1 = __float2bfloat16(gl1);
                uint32_t hw = (uint32_t)__bfloat16_as_ushort(hb0)
                            | ((uint32_t)__bfloat16_as_ushort(hb1) << 16);
                uint32_t lw = pkbf2(gl0 - __bfloat162float(hb0),
                                    gl1 - __bfloat162float(hb1));
                *(uint32_t*)(g_hhi + rowbase + c0) = hw;
                *(uint32_t*)(g_hlo + rowbase + c0) = lw;
            }
        }
    }
}

__global__ __launch_bounds__(256)
void gemm2_mma(const float* __restrict__ b2) {
    extern __shared__ char sm[];
    const int e    = blockIdx.x >> 6;
    const int tm   = blockIdx.x & 63;
    const int cnt  = g_cnt[e];
    const int row0 = tm * 128;
    if (row0 >= cnt) return;
    const int n0  = blockIdx.y * 128;
    const int tid = threadIdx.x;
    const int wid = tid >> 5, lane = tid & 31;
    const int wm = wid >> 2, wn = wid & 3;

    const uint32_t sbase = smem_u32(sm);

    const int crow = tid >> 2, cseg = tid & 3;
    const uint32_t so0 = crow * ROWB + cseg * 16;
    const uint32_t so1 = (crow + 64) * ROWB + cseg * 16;
    FragPtrs p;
    {
        size_t a0 = ((size_t)e * BQ + row0 + crow) * DEXP + cseg * 8;
        size_t a1 = ((size_t)e * BQ + row0 + crow + 64) * DEXP + cseg * 8;
        size_t b0 = ((size_t)e * DEXP + n0 + crow) * DEXP + cseg * 8;
        size_t b1o = ((size_t)e * DEXP + n0 + crow + 64) * DEXP + cseg * 8;
        p.ah0 = g_hhi + a0;  p.ah1 = g_hhi + a1;
        p.al0 = g_hlo + a0;  p.al1 = g_hlo + a1;
        p.bh0 = g_w2hi + b0; p.bh1 = g_w2hi + b1o;
        p.bl0 = g_w2lo + b0; p.bl1 = g_w2lo + b1o;
    }

    const uint32_t aoff = (wm * 64 + (lane & 15)) * ROWB + (lane >> 4) * 16;
    const uint32_t boff = (wn * 32 + ((lane >> 4) << 3) + (lane & 7)) * ROWB
                        + ((lane >> 3) & 1) * 16;

    float acc[4][4][4];
#pragma unroll
    for (int i = 0; i < 4; ++i)
#pragma unroll
        for (int j = 0; j < 4; ++j)
#pragma unroll
            for (int q = 0; q < 4; ++q) acc[i][j][q] = 0.0f;

    load_stage(sbase, p, 0, so0, so1);
    load_stage(sbase + STAGE_B, p, BK, so0, so1);
#pragma unroll 1
    for (int c = 0; c < NCHUNK; ++c) {
        if (c + 2 < NCHUNK) CPWAIT1(); else CPWAIT0();
        __syncthreads();
        if (c + 2 < NCHUNK)
            load_stage(sbase + ((c + 2) % 3) * STAGE_B, p, (c + 2) * BK, so0, so1);
        compute_chunk(sbase + (c % 3) * STAGE_B, aoff, boff, acc);
        __syncthreads();
    }

    // epilogue: + bias -> per-assignment scratch y
    float bias[4][2];
#pragma unroll
    for (int nt = 0; nt < 4; ++nt) {
        int c0 = n0 + wn * 32 + nt * 8 + (lane & 3) * 2;
        bias[nt][0] = b2[e * DEXP + c0];
        bias[nt][1] = b2[e * DEXP + c0 + 1];
    }
#pragma unroll
    for (int i = 0; i < 4; ++i) {
#pragma unroll
        for (int half = 0; half < 2; ++half) {
            int r = wm * 64 + i * 16 + (lane >> 2) + half * 8;
            if (row0 + r >= cnt) continue;
            float* yr = g_y + ((size_t)e * BQ + row0 + r) * DEXP;
#pragma unroll
            for (int nt = 0; nt < 4; ++nt) {
                int c0 = n0 + wn * 32 + nt * 8 + (lane & 3) * 2;
                float2 o;
                o.x = acc[i][nt][half * 2]     + bias[nt][0];
                o.y = acc[i][nt][half * 2 + 1] + bias[nt][1];
                *(float2*)(yr + c0) = o;
            }
        }
    }
}

// ---------------------------------------------------------------------------
// Kernel: combine the two expert contributions per token
// ---------------------------------------------------------------------------
__global__ __launch_bounds__(256)
void combine_kernel(float* __restrict__ out) {
    const int b = blockIdx.x, t = threadIdx.x;
    const int a0 = g_asn[2 * b], a1 = g_asn[2 * b + 1];
    const float w0 = g_wt[a0], w1 = g_wt[a1];
    const float4* y0 = (const float4*)(g_y + (size_t)a0 * DEXP);
    const float4* y1 = (const float4*)(g_y + (size_t)a1 * DEXP);
    float4 r0 = y0[t], r1 = y1[t], o;
    o.x = w0 * r0.x + w1 * r1.x;
    o.y = w0 * r0.y + w1 * r1.y;
    o.z = w0 * r0.z + w1 * r1.z;
    o.w = w0 * r0.w + w1 * r1.w;
    ((float4*)(out + (size_t)b * DEXP))[t] = o;
}

// ---------------------------------------------------------------------------
// Launch: output = [moe_output (B*DEXP) | gate_weights (B*NEXP)]
// ---------------------------------------------------------------------------
extern "C" void kernel_launch(void* const* d_in, const int* in_sizes, int n_in,
                              void* d_out, int out_size) {
    const float* x  = (const float*)d_in[0];
    const float* gw = (const float*)d_in[1];
    const float* w1 = (const float*)d_in[2];
    const float* b1 = (const float*)d_in[3];
    const float* w2 = (const float*)d_in[4];
    const float* b2 = (const float*)d_in[5];
    float* out      = (float*)d_out;
    float* gate_out = out + (size_t)BQ * DEXP;

    cudaFuncSetAttribute(gemm1_mma, cudaFuncAttributeMaxDynamicSharedMemorySize, SMEM_T);
    cudaFuncSetAttribute(gemm2_mma, cudaFuncAttributeMaxDynamicSharedMemorySize, SMEM_T);

    init_kernel<<<1, 32>>>();
    gate_kernel<<<BQ, 256>>>(x, gw, gate_out);
    convert_x_kernel<<<(BQ * DIN) / (256 * 4), 256>>>(x);
    convert_w_kernel<<<dim3(32, 32, 16), dim3(32, 8)>>>(w1, w2);

    dim3 grid(NEXP * (BQ / 128), DEXP / 128);
    gemm1_mma<<<grid, 256, SMEM_T>>>(b1);
    gemm2_mma<<<grid, 256, SMEM_T>>>(b2);
    combine_kernel<<<BQ, 256>>>(out);
}

// round 6
// speedup vs baseline: 1.7549x; 1.0214x over previous
#include <cuda_runtime.h>
#include <cuda_fp16.h>
#include <math.h>
#include <stdint.h>

#define BQ   8192
#define DIN  1024
#define NEXP 8
#define DEXP 1024

// GEMM tiling
#define BK        32
#define NCHUNK    32                  // 1024 / BK
#define ROWB      80                  // SMEM row stride bytes (32 fp16 + 8 pad)
#define ARR_B     (128 * ROWB)        // 10240 B per array
#define STAGE_B   (3 * ARR_B)         // Ah | Al | Bh = 30720 B
#define NSTAGE    3
#define TOK_OFF   (NSTAGE * STAGE_B)  // 92160
#define SMEM_T    (TOK_OFF + 1024)

// ---------------------------------------------------------------------------
// Static device scratch (sanctioned no-alloc path)
// ---------------------------------------------------------------------------
__device__ int   g_cnt[NEXP];
__device__ int   g_tok[NEXP * BQ];
__device__ float g_wt [NEXP * BQ];
__device__ int   g_asn[BQ * 2];
__device__ __align__(256) __half g_xhi[(size_t)BQ * DIN];
__device__ __align__(256) __half g_xlo[(size_t)BQ * DIN];
__device__ __align__(256) __half g_w1h[(size_t)NEXP * DIN * DEXP];
__device__ __align__(256) __half g_w2h[(size_t)NEXP * DEXP * DEXP];
__device__ __align__(256) __half g_hhi[(size_t)NEXP * BQ * DEXP];
__device__ __align__(256) __half g_hlo[(size_t)NEXP * BQ * DEXP];
__device__ __align__(256) float  g_y  [(size_t)NEXP * BQ * DEXP];

// ---------------------------------------------------------------------------
// PTX helpers (sm_103-base-target safe: mma.sync / ldmatrix / cp.async only)
// ---------------------------------------------------------------------------
__device__ __forceinline__ uint32_t smem_u32(const void* p) {
    uint32_t a;
    asm("{ .reg .u64 t; cvta.to.shared.u64 t, %1; cvt.u32.u64 %0, t; }"
        : "=r"(a) : "l"(p));
    return a;
}
#define CPASYNC(dst, src) \
    asm volatile("cp.async.cg.shared.global [%0], [%1], 16;" \
                 :: "r"(dst), "l"(src) : "memory")
#define CPCOMMIT()  asm volatile("cp.async.commit_group;" ::: "memory")
#define CPWAIT1()   asm volatile("cp.async.wait_group 1;" ::: "memory")
#define CPWAIT0()   asm volatile("cp.async.wait_group 0;" ::: "memory")

__device__ __forceinline__ void ldm4(uint32_t* r, uint32_t addr) {
    asm volatile("ldmatrix.sync.aligned.m8n8.x4.shared.b16 {%0,%1,%2,%3}, [%4];"
                 : "=r"(r[0]), "=r"(r[1]), "=r"(r[2]), "=r"(r[3]) : "r"(addr));
}
__device__ __forceinline__ void mma_f16(float* d, const uint32_t* a, const uint32_t* b) {
    asm volatile(
        "mma.sync.aligned.m16n8k16.row.col.f32.f16.f16.f32 "
        "{%0,%1,%2,%3}, {%4,%5,%6,%7}, {%8,%9}, {%0,%1,%2,%3};"
        : "+f"(d[0]), "+f"(d[1]), "+f"(d[2]), "+f"(d[3])
        : "r"(a[0]), "r"(a[1]), "r"(a[2]), "r"(a[3]), "r"(b[0]), "r"(b[1]));
}
__device__ __forceinline__ uint32_t pkh2(float a, float b) {
    return (uint32_t)__half_as_ushort(__float2half_rn(a))
         | ((uint32_t)__half_as_ushort(__float2half_rn(b)) << 16);
}

// ---------------------------------------------------------------------------
// Kernel: zero routing counters
// ---------------------------------------------------------------------------
__global__ void init_kernel() {
    if (threadIdx.x < NEXP) g_cnt[threadIdx.x] = 0;
}

// ---------------------------------------------------------------------------
// Kernel: gating (logits, top-2, softmax, routing, assignment ids)
// ---------------------------------------------------------------------------
__global__ __launch_bounds__(256)
void gate_kernel(const float* __restrict__ x, const float* __restrict__ gw,
                 float* __restrict__ gate_out) {
    const int b   = blockIdx.x;
    const int tid = threadIdx.x;
    const float* xr = x + (size_t)b * DIN;

    float acc[8];
#pragma unroll
    for (int e = 0; e < 8; e++) acc[e] = 0.0f;
    for (int k = tid; k < DIN; k += 256) {
        float xv = xr[k];
        float4 g0 = *(const float4*)(gw + k * 8);
        float4 g1 = *(const float4*)(gw + k * 8 + 4);
        acc[0] += xv * g0.x; acc[1] += xv * g0.y;
        acc[2] += xv * g0.z; acc[3] += xv * g0.w;
        acc[4] += xv * g1.x; acc[5] += xv * g1.y;
        acc[6] += xv * g1.z; acc[7] += xv * g1.w;
    }
#pragma unroll
    for (int e = 0; e < 8; e++)
#pragma unroll
        for (int off = 16; off > 0; off >>= 1)
            acc[e] += __shfl_down_sync(0xffffffffu, acc[e], off);

    __shared__ float wpart[8][8];
    __shared__ float logits[8];
    __shared__ float sw[2];
    __shared__ int   si[2];
    const int warp = tid >> 5, lane = tid & 31;
    if (lane == 0)
#pragma unroll
        for (int e = 0; e < 8; e++) wpart[warp][e] = acc[e];
    __syncthreads();
    if (tid < 8) {
        float s = 0.0f;
#pragma unroll
        for (int w = 0; w < 8; w++) s += wpart[w][tid];
        logits[tid] = s;
    }
    __syncthreads();

    if (tid == 0) {
        int i0 = 0; float v0 = logits[0];
#pragma unroll
        for (int e = 1; e < 8; e++) if (logits[e] > v0) { v0 = logits[e]; i0 = e; }
        int i1 = -1; float v1 = -3.4e38f;
#pragma unroll
        for (int e = 0; e < 8; e++)
            if (e != i0 && logits[e] > v1) { v1 = logits[e]; i1 = e; }
        float ex  = expf(v1 - v0);
        float inv = 1.0f / (1.0f + ex);
        float w0 = inv, w1 = ex * inv;
        si[0] = i0; si[1] = i1; sw[0] = w0; sw[1] = w1;
        int p0 = atomicAdd(&g_cnt[i0], 1);
        g_tok[i0 * BQ + p0] = b; g_wt[i0 * BQ + p0] = w0; g_asn[2 * b]     = i0 * BQ + p0;
        int p1 = atomicAdd(&g_cnt[i1], 1);
        g_tok[i1 * BQ + p1] = b; g_wt[i1 * BQ + p1] = w1; g_asn[2 * b + 1] = i1 * BQ + p1;
    }
    __syncthreads();
    if (tid < 8) {
        float v = (tid == si[0]) ? sw[0] : ((tid == si[1]) ? sw[1] : 0.0f);
        gate_out[(size_t)b * 8 + tid] = v;
    }
}

// ---------------------------------------------------------------------------
// Kernel: split x into fp16 hi/lo (A kept exact; hi + lo reconstructs ~fp32)
// ---------------------------------------------------------------------------
__global__ __launch_bounds__(256)
void convert_x_kernel(const float* __restrict__ x) {
    size_t i = ((size_t)blockIdx.x * 256 + threadIdx.x) * 4;
    float4 v = *(const float4*)(x + i);
    __half h0 = __float2half_rn(v.x), h1 = __float2half_rn(v.y);
    __half h2 = __float2half_rn(v.z), h3 = __float2half_rn(v.w);
    uint2 hp, lp;
    hp.x = (uint32_t)__half_as_ushort(h0) | ((uint32_t)__half_as_ushort(h1) << 16);
    hp.y = (uint32_t)__half_as_ushort(h2) | ((uint32_t)__half_as_ushort(h3) << 16);
    lp.x = pkh2(v.x - __half2float(h0), v.y - __half2float(h1));
    lp.y = pkh2(v.z - __half2float(h2), v.w - __half2float(h3));
    *(uint2*)(g_xhi + i) = hp;
    *(uint2*)(g_xlo + i) = lp;
}

// ---------------------------------------------------------------------------
// Kernel: transpose w1/w2 -> [e][n][k] fp16 (B side: single rounding)
// grid (32, 32, 16): z = mat*8 + e ; block (32, 8)
// ---------------------------------------------------------------------------
__global__ void convert_w_kernel(const float* __restrict__ w1,
                                 const float* __restrict__ w2) {
    __shared__ float t[32][33];
    const int z = blockIdx.z;
    const float* src = (z < 8 ? w1 : w2) + (size_t)(z & 7) * DIN * DEXP;
    __half* dh = (z < 8 ? g_w1h : g_w2h) + (size_t)(z & 7) * DIN * DEXP;
    const int n0 = blockIdx.x * 32, k0 = blockIdx.y * 32;
    const int tx = threadIdx.x, ty = threadIdx.y;
#pragma unroll
    for (int j = 0; j < 32; j += 8)
        t[ty + j][tx] = src[(size_t)(k0 + ty + j) * DEXP + n0 + tx];
    __syncthreads();
#pragma unroll
    for (int j = 0; j < 32; j += 8) {
        size_t o = (size_t)(n0 + ty + j) * DIN + k0 + tx;
        dh[o] = __float2half_rn(t[tx][ty + j]);
    }
}

// ---------------------------------------------------------------------------
// mma.sync GEMM kernels: 128x128 tile, BK=32, 3-stage cp.async pipeline.
// 8 warps: warp m = wid>>2 (64 rows), warp n = wid&3 (32 cols).
// fp16 2-term per k16: D += Ah*Bh + Al*Bh  (== A_exact * B_fp16)
// grid: x = e*64 + m_tile (early exit), y = n_tile (8).
// ---------------------------------------------------------------------------
struct FragPtrs {
    const __half *ah0, *ah1, *al0, *al1, *bh0, *bh1;
};

__device__ __forceinline__ void load_stage(uint32_t st, const FragPtrs& p,
                                           int k0, uint32_t so0, uint32_t so1) {
    CPASYNC(st + so0,              p.ah0 + k0);
    CPASYNC(st + so1,              p.ah1 + k0);
    CPASYNC(st + ARR_B + so0,      p.al0 + k0);
    CPASYNC(st + ARR_B + so1,      p.al1 + k0);
    CPASYNC(st + 2 * ARR_B + so0,  p.bh0 + k0);
    CPASYNC(st + 2 * ARR_B + so1,  p.bh1 + k0);
    CPCOMMIT();
}

__device__ __forceinline__ void compute_chunk(uint32_t st, uint32_t aoff,
                                              uint32_t boff, float acc[4][4][4]) {
#pragma unroll
    for (int kk = 0; kk < 2; ++kk) {
        uint32_t ah[4][4], al[4][4], bh[2][4];
#pragma unroll
        for (int i = 0; i < 4; ++i) {
            ldm4(ah[i], st + aoff + i * (16 * ROWB) + kk * 32);
            ldm4(al[i], st + ARR_B + aoff + i * (16 * ROWB) + kk * 32);
        }
#pragma unroll
        for (int pp = 0; pp < 2; ++pp)
            ldm4(bh[pp], st + 2 * ARR_B + boff + pp * (16 * ROWB) + kk * 32);
#pragma unroll
        for (int i = 0; i < 4; ++i)
#pragma unroll
            for (int nt = 0; nt < 4; ++nt) {
                const uint32_t* bhf = &bh[nt >> 1][(nt & 1) * 2];
                mma_f16(acc[i][nt], ah[i], bhf);
                mma_f16(acc[i][nt], al[i], bhf);
            }
    }
}

__global__ __launch_bounds__(256)
void gemm1_mma(const float* __restrict__ b1) {
    extern __shared__ char sm[];
    const int e    = blockIdx.x >> 6;
    const int tm   = blockIdx.x & 63;
    const int cnt  = g_cnt[e];
    const int row0 = tm * 128;
    if (row0 >= cnt) return;
    const int n0  = blockIdx.y * 128;
    const int tid = threadIdx.x;
    const int wid = tid >> 5, lane = tid & 31;
    const int wm = wid >> 2, wn = wid & 3;

    const uint32_t sbase = smem_u32(sm);
    int* tok_s = (int*)(sm + TOK_OFF);
    if (tid < 128) {
        int r = row0 + tid;
        tok_s[tid] = (r < cnt) ? g_tok[e * BQ + r] : g_tok[e * BQ + row0];
    }
    __syncthreads();

    const int crow = tid >> 2, cseg = tid & 3;
    const uint32_t so0 = crow * ROWB + cseg * 16;
    const uint32_t so1 = (crow + 64) * ROWB + cseg * 16;
    FragPtrs p;
    {
        size_t a0  = (size_t)tok_s[crow] * DIN + cseg * 8;
        size_t a1  = (size_t)tok_s[crow + 64] * DIN + cseg * 8;
        size_t b0  = ((size_t)e * DEXP + n0 + crow) * DIN + cseg * 8;
        size_t b1o = ((size_t)e * DEXP + n0 + crow + 64) * DIN + cseg * 8;
        p.ah0 = g_xhi + a0;  p.ah1 = g_xhi + a1;
        p.al0 = g_xlo + a0;  p.al1 = g_xlo + a1;
        p.bh0 = g_w1h + b0;  p.bh1 = g_w1h + b1o;
    }

    const uint32_t aoff = (wm * 64 + (lane & 15)) * ROWB + (lane >> 4) * 16;
    const uint32_t boff = (wn * 32 + ((lane >> 4) << 3) + (lane & 7)) * ROWB
                        + ((lane >> 3) & 1) * 16;

    float acc[4][4][4];
#pragma unroll
    for (int i = 0; i < 4; ++i)
#pragma unroll
        for (int j = 0; j < 4; ++j)
#pragma unroll
            for (int q = 0; q < 4; ++q) acc[i][j][q] = 0.0f;

    load_stage(sbase, p, 0, so0, so1);
    load_stage(sbase + STAGE_B, p, BK, so0, so1);
#pragma unroll 1
    for (int c = 0; c < NCHUNK; ++c) {
        if (c + 2 < NCHUNK) CPWAIT1(); else CPWAIT0();
        __syncthreads();
        if (c + 2 < NCHUNK)
            load_stage(sbase + ((c + 2) % 3) * STAGE_B, p, (c + 2) * BK, so0, so1);
        compute_chunk(sbase + (c % 3) * STAGE_B, aoff, boff, acc);
        __syncthreads();
    }

    // epilogue: bias + exact gelu, split to fp16 hi/lo, write h
    float bias[4][2];
#pragma unroll
    for (int nt = 0; nt < 4; ++nt) {
        int c0 = n0 + wn * 32 + nt * 8 + (lane & 3) * 2;
        bias[nt][0] = b1[e * DEXP + c0];
        bias[nt][1] = b1[e * DEXP + c0 + 1];
    }
#pragma unroll
    for (int i = 0; i < 4; ++i) {
#pragma unroll
        for (int half = 0; half < 2; ++half) {
            int r = wm * 64 + i * 16 + (lane >> 2) + half * 8;
            if (row0 + r >= cnt) continue;
            size_t rowbase = ((size_t)e * BQ + row0 + r) * DEXP;
#pragma unroll
            for (int nt = 0; nt < 4; ++nt) {
                int c0 = n0 + wn * 32 + nt * 8 + (lane & 3) * 2;
                float z0 = acc[i][nt][half * 2]     + bias[nt][0];
                float z1 = acc[i][nt][half * 2 + 1] + bias[nt][1];
                float gl0 = 0.5f * z0 * (1.0f + erff(z0 * 0.70710678118654752f));
                float gl1 = 0.5f * z1 * (1.0f + erff(z1 * 0.70710678118654752f));
                __half hb0 = __float2half_rn(gl0);
                __half hb1 = __float2half_rn(gl1);
                uint32_t hw = (uint32_t)__half_as_ushort(hb0)
                            | ((uint32_t)__half_as_ushort(hb1) << 16);
                uint32_t lw = pkh2(gl0 - __half2float(hb0),
                                   gl1 - __half2float(hb1));
                *(uint32_t*)(g_hhi + rowbase + c0) = hw;
                *(uint32_t*)(g_hlo + rowbase + c0) = lw;
            }
        }
    }
}

__global__ __launch_bounds__(256)
void gemm2_mma(const float* __restrict__ b2) {
    extern __shared__ char sm[];
    const int e    = blockIdx.x >> 6;
    const int tm   = blockIdx.x & 63;
    const int cnt  = g_cnt[e];
    const int row0 = tm * 128;
    if (row0 >= cnt) return;
    const int n0  = blockIdx.y * 128;
    const int tid = threadIdx.x;
    const int wid = tid >> 5, lane = tid & 31;
    const int wm = wid >> 2, wn = wid & 3;

    const uint32_t sbase = smem_u32(sm);

    const int crow = tid >> 2, cseg = tid & 3;
    const uint32_t so0 = crow * ROWB + cseg * 16;
    const uint32_t so1 = (crow + 64) * ROWB + cseg * 16;
    FragPtrs p;
    {
        size_t a0  = ((size_t)e * BQ + row0 + crow) * DEXP + cseg * 8;
        size_t a1  = ((size_t)e * BQ + row0 + crow + 64) * DEXP + cseg * 8;
        size_t b0  = ((size_t)e * DEXP + n0 + crow) * DEXP + cseg * 8;
        size_t b1o = ((size_t)e * DEXP + n0 + crow + 64) * DEXP + cseg * 8;
        p.ah0 = g_hhi + a0;  p.ah1 = g_hhi + a1;
        p.al0 = g_hlo + a0;  p.al1 = g_hlo + a1;
        p.bh0 = g_w2h + b0;  p.bh1 = g_w2h + b1o;
    }

    const uint32_t aoff = (wm * 64 + (lane & 15)) * ROWB + (lane >> 4) * 16;
    const uint32_t boff = (wn * 32 + ((lane >> 4) << 3) + (lane & 7)) * ROWB
                        + ((lane >> 3) & 1) * 16;

    float acc[4][4][4];
#pragma unroll
    for (int i = 0; i < 4; ++i)
#pragma unroll
        for (int j = 0; j < 4; ++j)
#pragma unroll
            for (int q = 0; q < 4; ++q) acc[i][j][q] = 0.0f;

    load_stage(sbase, p, 0, so0, so1);
    load_stage(sbase + STAGE_B, p, BK, so0, so1);
#pragma unroll 1
    for (int c = 0; c < NCHUNK; ++c) {
        if (c + 2 < NCHUNK) CPWAIT1(); else CPWAIT0();
        __syncthreads();
        if (c + 2 < NCHUNK)
            load_stage(sbase + ((c + 2) % 3) * STAGE_B, p, (c + 2) * BK, so0, so1);
        compute_chunk(sbase + (c % 3) * STAGE_B, aoff, boff, acc);
        __syncthreads();
    }

    // epilogue: + bias -> per-assignment scratch y
    float bias[4][2];
#pragma unroll
    for (int nt = 0; nt < 4; ++nt) {
        int c0 = n0 + wn * 32 + nt * 8 + (lane & 3) * 2;
        bias[nt][0] = b2[e * DEXP + c0];
        bias[nt][1] = b2[e * DEXP + c0 + 1];
    }
#pragma unroll
    for (int i = 0; i < 4; ++i) {
#pragma unroll
        for (int half = 0; half < 2; ++half) {
            int r = wm * 64 + i * 16 + (lane >> 2) + half * 8;
            if (row0 + r >= cnt) continue;
            float* yr = g_y + ((size_t)e * BQ + row0 + r) * DEXP;
#pragma unroll
            for (int nt = 0; nt < 4; ++nt) {
                int c0 = n0 + wn * 32 + nt * 8 + (lane & 3) * 2;
                float2 o;
                o.x = acc[i][nt][half * 2]     + bias[nt][0];
                o.y = acc[i][nt][half * 2 + 1] + bias[nt][1];
                *(float2*)(yr + c0) = o;
            }
        }
    }
}

// ---------------------------------------------------------------------------
// Kernel: combine the two expert contributions per token
// ---------------------------------------------------------------------------
__global__ __launch_bounds__(256)
void combine_kernel(float* __restrict__ out) {
    const int b = blockIdx.x, t = threadIdx.x;
    const int a0 = g_asn[2 * b], a1 = g_asn[2 * b + 1];
    const float w0 = g_wt[a0], w1 = g_wt[a1];
    const float4* y0 = (const float4*)(g_y + (size_t)a0 * DEXP);
    const float4* y1 = (const float4*)(g_y + (size_t)a1 * DEXP);
    float4 r0 = y0[t], r1 = y1[t], o;
    o.x = w0 * r0.x + w1 * r1.x;
    o.y = w0 * r0.y + w1 * r1.y;
    o.z = w0 * r0.z + w1 * r1.z;
    o.w = w0 * r0.w + w1 * r1.w;
    ((float4*)(out + (size_t)b * DEXP))[t] = o;
}

// ---------------------------------------------------------------------------
// Launch: output = [moe_output (B*DEXP) | gate_weights (B*NEXP)]
// ---------------------------------------------------------------------------
extern "C" void kernel_launch(void* const* d_in, const int* in_sizes, int n_in,
                              void* d_out, int out_size) {
    const float* x  = (const float*)d_in[0];
    const float* gw = (const float*)d_in[1];
    const float* w1 = (const float*)d_in[2];
    const float* b1 = (const float*)d_in[3];
    const float* w2 = (const float*)d_in[4];
    const float* b2 = (const float*)d_in[5];
    float* out      = (float*)d_out;
    float* gate_out = out + (size_t)BQ * DEXP;

    cudaFuncSetAttribute(gemm1_mma, cudaFuncAttributeMaxDynamicSharedMemorySize, SMEM_T);
    cudaFuncSetAttribute(gemm2_mma, cudaFuncAttributeMaxDynamicSharedMemorySize, SMEM_T);

    init_kernel<<<1, 32>>>();
    gate_kernel<<<BQ, 256>>>(x, gw, gate_out);
    convert_x_kernel<<<(BQ * DIN) / (256 * 4), 256>>>(x);
    convert_w_kernel<<<dim3(32, 32, 16), dim3(32, 8)>>>(w1, w2);

    dim3 grid(NEXP * (BQ / 128), DEXP / 128);
    gemm1_mma<<<grid, 256, SMEM_T>>>(b1);
    gemm2_mma<<<grid, 256, SMEM_T>>>(b2);
    combine_kernel<<<BQ, 256>>>(out);
}

// round 7
// speedup vs baseline: 2.2348x; 1.2735x over previous
#include <cuda_runtime.h>
#include <cuda_fp16.h>
#include <math.h>
#include <stdint.h>

#define BQ   8192
#define DIN  1024
#define NEXP 8
#define DEXP 1024

// GEMM tiling
#define BK        32
#define NCHUNK    32                  // 1024 / BK
#define ROWB      80                  // SMEM row stride bytes (32 fp16 + 8 pad)
#define ARR_B     (128 * ROWB)        // 10240 B per array
#define STAGE_B   (3 * ARR_B)         // Ah | Al | Bh = 30720 B
#define NSTAGE    5
#define TOK_OFF   (NSTAGE * STAGE_B)  // 153600
#define SMEM_T    (TOK_OFF + 1024)

// ---------------------------------------------------------------------------
// Static device scratch (sanctioned no-alloc path)
// ---------------------------------------------------------------------------
__device__ int   g_cnt[NEXP];
__device__ int   g_tok[NEXP * BQ];
__device__ float g_wt [NEXP * BQ];
__device__ int   g_asn[BQ * 2];
__device__ __align__(256) __half g_xhi[(size_t)BQ * DIN];
__device__ __align__(256) __half g_xlo[(size_t)BQ * DIN];
__device__ __align__(256) __half g_w1h[(size_t)NEXP * DIN * DEXP];
__device__ __align__(256) __half g_w2h[(size_t)NEXP * DEXP * DEXP];
__device__ __align__(256) __half g_hhi[(size_t)NEXP * BQ * DEXP];
__device__ __align__(256) __half g_hlo[(size_t)NEXP * BQ * DEXP];
__device__ __align__(256) float  g_y  [(size_t)NEXP * BQ * DEXP];

// ---------------------------------------------------------------------------
// PTX helpers (sm_103-base-target safe: mma.sync / ldmatrix / cp.async only)
// ---------------------------------------------------------------------------
__device__ __forceinline__ uint32_t smem_u32(const void* p) {
    uint32_t a;
    asm("{ .reg .u64 t; cvta.to.shared.u64 t, %1; cvt.u32.u64 %0, t; }"
        : "=r"(a) : "l"(p));
    return a;
}
#define CPASYNC(dst, src) \
    asm volatile("cp.async.cg.shared.global [%0], [%1], 16;" \
                 :: "r"(dst), "l"(src) : "memory")
#define CPCOMMIT()  asm volatile("cp.async.commit_group;" ::: "memory")
#define CPWAIT3()   asm volatile("cp.async.wait_group 3;" ::: "memory")
#define CPWAIT0()   asm volatile("cp.async.wait_group 0;" ::: "memory")

__device__ __forceinline__ void ldm4(uint32_t* r, uint32_t addr) {
    asm volatile("ldmatrix.sync.aligned.m8n8.x4.shared.b16 {%0,%1,%2,%3}, [%4];"
                 : "=r"(r[0]), "=r"(r[1]), "=r"(r[2]), "=r"(r[3]) : "r"(addr));
}
__device__ __forceinline__ void mma_f16(float* d, const uint32_t* a, const uint32_t* b) {
    asm volatile(
        "mma.sync.aligned.m16n8k16.row.col.f32.f16.f16.f32 "
        "{%0,%1,%2,%3}, {%4,%5,%6,%7}, {%8,%9}, {%0,%1,%2,%3};"
        : "+f"(d[0]), "+f"(d[1]), "+f"(d[2]), "+f"(d[3])
        : "r"(a[0]), "r"(a[1]), "r"(a[2]), "r"(a[3]), "r"(b[0]), "r"(b[1]));
}
__device__ __forceinline__ uint32_t pkh2(float a, float b) {
    return (uint32_t)__half_as_ushort(__float2half_rn(a))
         | ((uint32_t)__half_as_ushort(__float2half_rn(b)) << 16);
}

// ---------------------------------------------------------------------------
// Kernel: zero routing counters
// ---------------------------------------------------------------------------
__global__ void init_kernel() {
    if (threadIdx.x < NEXP) g_cnt[threadIdx.x] = 0;
}

// ---------------------------------------------------------------------------
// Kernel: gating (logits, top-2, softmax, routing, assignment ids)
// ---------------------------------------------------------------------------
__global__ __launch_bounds__(256)
void gate_kernel(const float* __restrict__ x, const float* __restrict__ gw,
                 float* __restrict__ gate_out) {
    const int b   = blockIdx.x;
    const int tid = threadIdx.x;
    const float* xr = x + (size_t)b * DIN;

    float acc[8];
#pragma unroll
    for (int e = 0; e < 8; e++) acc[e] = 0.0f;
    for (int k = tid; k < DIN; k += 256) {
        float xv = xr[k];
        float4 g0 = *(const float4*)(gw + k * 8);
        float4 g1 = *(const float4*)(gw + k * 8 + 4);
        acc[0] += xv * g0.x; acc[1] += xv * g0.y;
        acc[2] += xv * g0.z; acc[3] += xv * g0.w;
        acc[4] += xv * g1.x; acc[5] += xv * g1.y;
        acc[6] += xv * g1.z; acc[7] += xv * g1.w;
    }
#pragma unroll
    for (int e = 0; e < 8; e++)
#pragma unroll
        for (int off = 16; off > 0; off >>= 1)
            acc[e] += __shfl_down_sync(0xffffffffu, acc[e], off);

    __shared__ float wpart[8][8];
    __shared__ float logits[8];
    __shared__ float sw[2];
    __shared__ int   si[2];
    const int warp = tid >> 5, lane = tid & 31;
    if (lane == 0)
#pragma unroll
        for (int e = 0; e < 8; e++) wpart[warp][e] = acc[e];
    __syncthreads();
    if (tid < 8) {
        float s = 0.0f;
#pragma unroll
        for (int w = 0; w < 8; w++) s += wpart[w][tid];
        logits[tid] = s;
    }
    __syncthreads();

    if (tid == 0) {
        int i0 = 0; float v0 = logits[0];
#pragma unroll
        for (int e = 1; e < 8; e++) if (logits[e] > v0) { v0 = logits[e]; i0 = e; }
        int i1 = -1; float v1 = -3.4e38f;
#pragma unroll
        for (int e = 0; e < 8; e++)
            if (e != i0 && logits[e] > v1) { v1 = logits[e]; i1 = e; }
        float ex  = expf(v1 - v0);
        float inv = 1.0f / (1.0f + ex);
        float w0 = inv, w1 = ex * inv;
        si[0] = i0; si[1] = i1; sw[0] = w0; sw[1] = w1;
        int p0 = atomicAdd(&g_cnt[i0], 1);
        g_tok[i0 * BQ + p0] = b; g_wt[i0 * BQ + p0] = w0; g_asn[2 * b]     = i0 * BQ + p0;
        int p1 = atomicAdd(&g_cnt[i1], 1);
        g_tok[i1 * BQ + p1] = b; g_wt[i1 * BQ + p1] = w1; g_asn[2 * b + 1] = i1 * BQ + p1;
    }
    __syncthreads();
    if (tid < 8) {
        float v = (tid == si[0]) ? sw[0] : ((tid == si[1]) ? sw[1] : 0.0f);
        gate_out[(size_t)b * 8 + tid] = v;
    }
}

// ---------------------------------------------------------------------------
// Kernel: split x into fp16 hi/lo (A kept exact; hi + lo reconstructs ~fp32)
// ---------------------------------------------------------------------------
__global__ __launch_bounds__(256)
void convert_x_kernel(const float* __restrict__ x) {
    size_t i = ((size_t)blockIdx.x * 256 + threadIdx.x) * 4;
    float4 v = *(const float4*)(x + i);
    __half h0 = __float2half_rn(v.x), h1 = __float2half_rn(v.y);
    __half h2 = __float2half_rn(v.z), h3 = __float2half_rn(v.w);
    uint2 hp, lp;
    hp.x = (uint32_t)__half_as_ushort(h0) | ((uint32_t)__half_as_ushort(h1) << 16);
    hp.y = (uint32_t)__half_as_ushort(h2) | ((uint32_t)__half_as_ushort(h3) << 16);
    lp.x = pkh2(v.x - __half2float(h0), v.y - __half2float(h1));
    lp.y = pkh2(v.z - __half2float(h2), v.w - __half2float(h3));
    *(uint2*)(g_xhi + i) = hp;
    *(uint2*)(g_xlo + i) = lp;
}

// ---------------------------------------------------------------------------
// Kernel: transpose w1/w2 -> [e][n][k] fp16 (B side: single rounding)
// ---------------------------------------------------------------------------
__global__ void convert_w_kernel(const float* __restrict__ w1,
                                 const float* __restrict__ w2) {
    __shared__ float t[32][33];
    const int z = blockIdx.z;
    const float* src = (z < 8 ? w1 : w2) + (size_t)(z & 7) * DIN * DEXP;
    __half* dh = (z < 8 ? g_w1h : g_w2h) + (size_t)(z & 7) * DIN * DEXP;
    const int n0 = blockIdx.x * 32, k0 = blockIdx.y * 32;
    const int tx = threadIdx.x, ty = threadIdx.y;
#pragma unroll
    for (int j = 0; j < 32; j += 8)
        t[ty + j][tx] = src[(size_t)(k0 + ty + j) * DEXP + n0 + tx];
    __syncthreads();
#pragma unroll
    for (int j = 0; j < 32; j += 8) {
        size_t o = (size_t)(n0 + ty + j) * DIN + k0 + tx;
        dh[o] = __float2half_rn(t[tx][ty + j]);
    }
}

// ---------------------------------------------------------------------------
// mma.sync GEMM kernels: 128x128 tile, BK=32, 5-stage cp.async pipeline.
// 512 threads / 16 warps: warp m = wid>>2 (32 rows), warp n = wid&3 (32 cols)
// -> 4 warps per SMSP for latency hiding, 32-reg accumulators.
// fp16 2-term per k16: D += Ah*Bh + Al*Bh  (== A_exact * B_fp16)
// grid: x = e*64 + m_tile (early exit), y = n_tile (8).
// ---------------------------------------------------------------------------
struct FragPtrs { const __half *ah, *al, *bh; };

__device__ __forceinline__ void load_stage(uint32_t st, const FragPtrs& p,
                                           int k0, uint32_t so) {
    CPASYNC(st + so,             p.ah + k0);
    CPASYNC(st + ARR_B + so,     p.al + k0);
    CPASYNC(st + 2 * ARR_B + so, p.bh + k0);
    CPCOMMIT();
}

__device__ __forceinline__ void compute_chunk(uint32_t st, uint32_t aoff,
                                              uint32_t boff, float acc[2][4][4]) {
#pragma unroll
    for (int kk = 0; kk < 2; ++kk) {
        uint32_t ah[2][4], al[2][4], bh[2][4];
#pragma unroll
        for (int i = 0; i < 2; ++i) {
            ldm4(ah[i], st + aoff + i * (16 * ROWB) + kk * 32);
            ldm4(al[i], st + ARR_B + aoff + i * (16 * ROWB) + kk * 32);
        }
#pragma unroll
        for (int pp = 0; pp < 2; ++pp)
            ldm4(bh[pp], st + 2 * ARR_B + boff + pp * (16 * ROWB) + kk * 32);
#pragma unroll
        for (int i = 0; i < 2; ++i)
#pragma unroll
            for (int nt = 0; nt < 4; ++nt) {
                const uint32_t* bhf = &bh[nt >> 1][(nt & 1) * 2];
                mma_f16(acc[i][nt], ah[i], bhf);
                mma_f16(acc[i][nt], al[i], bhf);
            }
    }
}

__global__ __launch_bounds__(512)
void gemm1_mma(const float* __restrict__ b1) {
    extern __shared__ char sm[];
    const int e    = blockIdx.x >> 6;
    const int tm   = blockIdx.x & 63;
    const int cnt  = g_cnt[e];
    const int row0 = tm * 128;
    if (row0 >= cnt) return;
    const int n0  = blockIdx.y * 128;
    const int tid = threadIdx.x;
    const int wid = tid >> 5, lane = tid & 31;
    const int wm = wid >> 2, wn = wid & 3;

    const uint32_t sbase = smem_u32(sm);
    int* tok_s = (int*)(sm + TOK_OFF);
    if (tid < 128) {
        int r = row0 + tid;
        tok_s[tid] = (r < cnt) ? g_tok[e * BQ + r] : g_tok[e * BQ + row0];
    }
    __syncthreads();

    // cp.async: thread covers one row (crow), one 16B segment (cseg)
    const int crow = tid >> 2, cseg = tid & 3;
    const uint32_t so = crow * ROWB + cseg * 16;
    FragPtrs p;
    p.ah = g_xhi + (size_t)tok_s[crow] * DIN + cseg * 8;
    p.al = g_xlo + (size_t)tok_s[crow] * DIN + cseg * 8;
    p.bh = g_w1h + ((size_t)e * DEXP + n0 + crow) * DIN + cseg * 8;

    const uint32_t aoff = (wm * 32 + (lane & 15)) * ROWB + (lane >> 4) * 16;
    const uint32_t boff = (wn * 32 + ((lane >> 4) << 3) + (lane & 7)) * ROWB
                        + ((lane >> 3) & 1) * 16;

    float acc[2][4][4];
#pragma unroll
    for (int i = 0; i < 2; ++i)
#pragma unroll
        for (int j = 0; j < 4; ++j)
#pragma unroll
            for (int q = 0; q < 4; ++q) acc[i][j][q] = 0.0f;

#pragma unroll
    for (int s = 0; s < NSTAGE - 1; ++s)
        load_stage(sbase + s * STAGE_B, p, s * BK, so);
#pragma unroll 1
    for (int c = 0; c < NCHUNK; ++c) {
        if (c + NSTAGE - 1 < NCHUNK) CPWAIT3(); else CPWAIT0();
        __syncthreads();
        if (c + NSTAGE - 1 < NCHUNK)
            load_stage(sbase + ((c + NSTAGE - 1) % NSTAGE) * STAGE_B, p,
                       (c + NSTAGE - 1) * BK, so);
        compute_chunk(sbase + (c % NSTAGE) * STAGE_B, aoff, boff, acc);
        __syncthreads();
    }

    // epilogue: bias + exact gelu, split to fp16 hi/lo, write h
    float bias[4][2];
#pragma unroll
    for (int nt = 0; nt < 4; ++nt) {
        int c0 = n0 + wn * 32 + nt * 8 + (lane & 3) * 2;
        bias[nt][0] = b1[e * DEXP + c0];
        bias[nt][1] = b1[e * DEXP + c0 + 1];
    }
#pragma unroll
    for (int i = 0; i < 2; ++i) {
#pragma unroll
        for (int half = 0; half < 2; ++half) {
            int r = wm * 32 + i * 16 + (lane >> 2) + half * 8;
            if (row0 + r >= cnt) continue;
            size_t rowbase = ((size_t)e * BQ + row0 + r) * DEXP;
#pragma unroll
            for (int nt = 0; nt < 4; ++nt) {
                int c0 = n0 + wn * 32 + nt * 8 + (lane & 3) * 2;
                float z0 = acc[i][nt][half * 2]     + bias[nt][0];
                float z1 = acc[i][nt][half * 2 + 1] + bias[nt][1];
                float gl0 = 0.5f * z0 * (1.0f + erff(z0 * 0.70710678118654752f));
                float gl1 = 0.5f * z1 * (1.0f + erff(z1 * 0.70710678118654752f));
                __half hb0 = __float2half_rn(gl0);
                __half hb1 = __float2half_rn(gl1);
                uint32_t hw = (uint32_t)__half_as_ushort(hb0)
                            | ((uint32_t)__half_as_ushort(hb1) << 16);
                uint32_t lw = pkh2(gl0 - __half2float(hb0),
                                   gl1 - __half2float(hb1));
                *(uint32_t*)(g_hhi + rowbase + c0) = hw;
                *(uint32_t*)(g_hlo + rowbase + c0) = lw;
            }
        }
    }
}

__global__ __launch_bounds__(512)
void gemm2_mma(const float* __restrict__ b2) {
    extern __shared__ char sm[];
    const int e    = blockIdx.x >> 6;
    const int tm   = blockIdx.x & 63;
    const int cnt  = g_cnt[e];
    const int row0 = tm * 128;
    if (row0 >= cnt) return;
    const int n0  = blockIdx.y * 128;
    const int tid = threadIdx.x;
    const int wid = tid >> 5, lane = tid & 31;
    const int wm = wid >> 2, wn = wid & 3;

    const uint32_t sbase = smem_u32(sm);

    const int crow = tid >> 2, cseg = tid & 3;
    const uint32_t so = crow * ROWB + cseg * 16;
    FragPtrs p;
    p.ah = g_hhi + ((size_t)e * BQ + row0 + crow) * DEXP + cseg * 8;
    p.al = g_hlo + ((size_t)e * BQ + row0 + crow) * DEXP + cseg * 8;
    p.bh = g_w2h + ((size_t)e * DEXP + n0 + crow) * DEXP + cseg * 8;

    const uint32_t aoff = (wm * 32 + (lane & 15)) * ROWB + (lane >> 4) * 16;
    const uint32_t boff = (wn * 32 + ((lane >> 4) << 3) + (lane & 7)) * ROWB
                        + ((lane >> 3) & 1) * 16;

    float acc[2][4][4];
#pragma unroll
    for (int i = 0; i < 2; ++i)
#pragma unroll
        for (int j = 0; j < 4; ++j)
#pragma unroll
            for (int q = 0; q < 4; ++q) acc[i][j][q] = 0.0f;

#pragma unroll
    for (int s = 0; s < NSTAGE - 1; ++s)
        load_stage(sbase + s * STAGE_B, p, s * BK, so);
#pragma unroll 1
    for (int c = 0; c < NCHUNK; ++c) {
        if (c + NSTAGE - 1 < NCHUNK) CPWAIT3(); else CPWAIT0();
        __syncthreads();
        if (c + NSTAGE - 1 < NCHUNK)
            load_stage(sbase + ((c + NSTAGE - 1) % NSTAGE) * STAGE_B, p,
                       (c + NSTAGE - 1) * BK, so);
        compute_chunk(sbase + (c % NSTAGE) * STAGE_B, aoff, boff, acc);
        __syncthreads();
    }

    // epilogue: + bias -> per-assignment scratch y
    float bias[4][2];
#pragma unroll
    for (int nt = 0; nt < 4; ++nt) {
        int c0 = n0 + wn * 32 + nt * 8 + (lane & 3) * 2;
        bias[nt][0] = b2[e * DEXP + c0];
        bias[nt][1] = b2[e * DEXP + c0 + 1];
    }
#pragma unroll
    for (int i = 0; i < 2; ++i) {
#pragma unroll
        for (int half = 0; half < 2; ++half) {
            int r = wm * 32 + i * 16 + (lane >> 2) + half * 8;
            if (row0 + r >= cnt) continue;
            float* yr = g_y + ((size_t)e * BQ + row0 + r) * DEXP;
#pragma unroll
            for (int nt = 0; nt < 4; ++nt) {
                int c0 = n0 + wn * 32 + nt * 8 + (lane & 3) * 2;
                float2 o;
                o.x = acc[i][nt][half * 2]     + bias[nt][0];
                o.y = acc[i][nt][half * 2 + 1] + bias[nt][1];
                *(float2*)(yr + c0) = o;
            }
        }
    }
}

// ---------------------------------------------------------------------------
// Kernel: combine the two expert contributions per token
// ---------------------------------------------------------------------------
__global__ __launch_bounds__(256)
void combine_kernel(float* __restrict__ out) {
    const int b = blockIdx.x, t = threadIdx.x;
    const int a0 = g_asn[2 * b], a1 = g_asn[2 * b + 1];
    const float w0 = g_wt[a0], w1 = g_wt[a1];
    const float4* y0 = (const float4*)(g_y + (size_t)a0 * DEXP);
    const float4* y1 = (const float4*)(g_y + (size_t)a1 * DEXP);
    float4 r0 = y0[t], r1 = y1[t], o;
    o.x = w0 * r0.x + w1 * r1.x;
    o.y = w0 * r0.y + w1 * r1.y;
    o.z = w0 * r0.z + w1 * r1.z;
    o.w = w0 * r0.w + w1 * r1.w;
    ((float4*)(out + (size_t)b * DEXP))[t] = o;
}

// ---------------------------------------------------------------------------
// Launch: output = [moe_output (B*DEXP) | gate_weights (B*NEXP)]
// ---------------------------------------------------------------------------
extern "C" void kernel_launch(void* const* d_in, const int* in_sizes, int n_in,
                              void* d_out, int out_size) {
    const float* x  = (const float*)d_in[0];
    const float* gw = (const float*)d_in[1];
    const float* w1 = (const float*)d_in[2];
    const float* b1 = (const float*)d_in[3];
    const float* w2 = (const float*)d_in[4];
    const float* b2 = (const float*)d_in[5];
    float* out      = (float*)d_out;
    float* gate_out = out + (size_t)BQ * DEXP;

    cudaFuncSetAttribute(gemm1_mma, cudaFuncAttributeMaxDynamicSharedMemorySize, SMEM_T);
    cudaFuncSetAttribute(gemm2_mma, cudaFuncAttributeMaxDynamicSharedMemorySize, SMEM_T);

    init_kernel<<<1, 32>>>();
    gate_kernel<<<BQ, 256>>>(x, gw, gate_out);
    convert_x_kernel<<<(BQ * DIN) / (256 * 4), 256>>>(x);
    convert_w_kernel<<<dim3(32, 32, 16), dim3(32, 8)>>>(w1, w2);

    dim3 grid(NEXP * (BQ / 128), DEXP / 128);
    gemm1_mma<<<grid, 512, SMEM_T>>>(b1);
    gemm2_mma<<<grid, 512, SMEM_T>>>(b2);
    combine_kernel<<<BQ, 256>>>(out);
}